// round 14
// baseline (speedup 1.0000x reference)
#include <cuda_runtime.h>
#include <math.h>

// Problem constants (fixed by the dataset)
#define NN 100000
#define NE 1600000
#define NG 128
#define F1 128   // IN_FEATS
#define F2 64    // OUT_FEATS

// ---------------- scratch (static device allocations are allowed) ----------
__device__ int   g_deg_out[NN];
__device__ int   g_deg_in[NN];
__device__ float g_nsrc[NN];
__device__ float g_ndst[NN];
__device__ int   g_off[NN + 1];
__device__ int   g_cur[NN];
__device__ int   g_esrc[NE];                    // src ids sorted by dst (CSR payload)
__device__ float g_h [(size_t)NN * F1];         // GEMM output buffer (reused: 128w then 64w)
__device__ float g_x1[(size_t)NN * F1];         // layer-1 activation
__device__ float g_h2[(size_t)NN * F2];         // layer-2 activation

// ---------------- small prep kernels ---------------------------------------
__global__ void zero_deg_kernel() {
    int i = blockIdx.x * blockDim.x + threadIdx.x;
    if (i < NN) { g_deg_out[i] = 0; g_deg_in[i] = 0; }
}

__global__ void degree_kernel(const int* __restrict__ src, const int* __restrict__ dst) {
    int i = blockIdx.x * blockDim.x + threadIdx.x;
    if (i < NE) {
        atomicAdd(&g_deg_out[src[i]], 1);
        atomicAdd(&g_deg_in [dst[i]], 1);
    }
}

__global__ void norm_kernel() {
    int i = blockIdx.x * blockDim.x + threadIdx.x;
    if (i < NN) {
        g_nsrc[i] = rsqrtf(fmaxf((float)g_deg_out[i], 1.0f));
        g_ndst[i] = rsqrtf(fmaxf((float)g_deg_in [i], 1.0f));
    }
}

// Single-block exclusive scan of g_deg_in -> g_off (and g_cur copy).
__global__ void scan_kernel() {
    __shared__ int part[1024];
    const int tid = threadIdx.x;
    const int CH  = (NN + 1023) / 1024;   // 98
    int start = tid * CH;
    int end   = start + CH; if (end > NN) end = NN;
    int s = 0;
    for (int i = start; i < end; i++) s += g_deg_in[i];
    part[tid] = s;
    __syncthreads();
    // Hillis-Steele inclusive scan
    for (int off = 1; off < 1024; off <<= 1) {
        int v = part[tid];
        int u = (tid >= off) ? part[tid - off] : 0;
        __syncthreads();
        part[tid] = v + u;
        __syncthreads();
    }
    int run = (tid > 0) ? part[tid - 1] : 0;
    for (int i = start; i < end; i++) {
        g_off[i] = run; g_cur[i] = run;
        run += g_deg_in[i];
    }
    if (tid == 1023) g_off[NN] = part[1023];
}

__global__ void bucket_kernel(const int* __restrict__ src, const int* __restrict__ dst) {
    int i = blockIdx.x * blockDim.x + threadIdx.x;
    if (i < NE) {
        int p = atomicAdd(&g_cur[dst[i]], 1);
        g_esrc[p] = src[i];
    }
}

// ---------------- GEMM: C[n, COLS] = (A[n,128] * nsrc[n]) @ W[128, COLS] ----
// 256 threads/block, ROWS rows per block, 4x8 register tile per thread.
// W resident in SMEM; A tile staged (row-padded to 132 floats to kill bank
// conflicts on the per-k scalar broadcasts while keeping float4 staging).
template <int ROWS, int COLS>
__global__ void __launch_bounds__(256) gemm_kernel(
    const float* __restrict__ A, const float* __restrict__ W,
    float* __restrict__ C, int nrows)
{
    extern __shared__ float smem[];
    float* Ws = smem;                 // [128][COLS]
    float* As = smem + 128 * COLS;    // [ROWS][132]
    const int tid  = threadIdx.x;
    const int row0 = blockIdx.x * ROWS;

    // stage W (contiguous copy, 16B vectors)
    for (int i = tid * 4; i < 128 * COLS; i += 256 * 4)
        *(float4*)&Ws[i] = *(const float4*)&W[i];

    // stage A, scaled by nsrc, zero-padded past nrows
    for (int i = tid; i < ROWS * 32; i += 256) {
        int r  = i >> 5;
        int kq = (i & 31) << 2;
        int gr = row0 + r;
        float4 v = make_float4(0.f, 0.f, 0.f, 0.f);
        float  nv = 0.f;
        if (gr < nrows) { v = *(const float4*)&A[(size_t)gr * 128 + kq]; nv = g_nsrc[gr]; }
        float4 sv = make_float4(v.x * nv, v.y * nv, v.z * nv, v.w * nv);
        *(float4*)&As[r * 132 + kq] = sv;
    }
    __syncthreads();

    constexpr int CG = COLS / 8;
    const int c0 = (tid % CG) * 8;
    const int r0 = (tid / CG) * 4;

    float acc[4][8];
    #pragma unroll
    for (int r = 0; r < 4; r++)
        #pragma unroll
        for (int c = 0; c < 8; c++) acc[r][c] = 0.f;

    #pragma unroll 8
    for (int k = 0; k < 128; k++) {
        float a0 = As[(r0 + 0) * 132 + k];
        float a1 = As[(r0 + 1) * 132 + k];
        float a2 = As[(r0 + 2) * 132 + k];
        float a3 = As[(r0 + 3) * 132 + k];
        float4 b0 = *(const float4*)&Ws[k * COLS + c0];
        float4 b1 = *(const float4*)&Ws[k * COLS + c0 + 4];
        float a[4] = {a0, a1, a2, a3};
        float b[8] = {b0.x, b0.y, b0.z, b0.w, b1.x, b1.y, b1.z, b1.w};
        #pragma unroll
        for (int r = 0; r < 4; r++)
            #pragma unroll
            for (int c = 0; c < 8; c++)
                acc[r][c] = fmaf(a[r], b[c], acc[r][c]);
    }

    #pragma unroll
    for (int r = 0; r < 4; r++) {
        int gr = row0 + r0 + r;
        if (gr < nrows) {
            *(float4*)&C[(size_t)gr * COLS + c0]     =
                make_float4(acc[r][0], acc[r][1], acc[r][2], acc[r][3]);
            *(float4*)&C[(size_t)gr * COLS + c0 + 4] =
                make_float4(acc[r][4], acc[r][5], acc[r][6], acc[r][7]);
        }
    }
}

// ---------------- CSR gather aggregation + norm_dst + bias + relu ----------
// warp per node, F=128: lane owns 4 contiguous floats (float4 loads)
__global__ void __launch_bounds__(256) agg128_kernel(
    const float* __restrict__ h, const float* __restrict__ bias,
    float* __restrict__ out)
{
    int gw   = (blockIdx.x * 256 + threadIdx.x) >> 5;
    int lane = threadIdx.x & 31;
    if (gw >= NN) return;
    int base = lane * 4;
    float a0 = 0.f, a1 = 0.f, a2 = 0.f, a3 = 0.f;
    int e = g_off[gw], end = g_off[gw + 1];
    for (; e + 1 < end; e += 2) {
        int s0 = g_esrc[e], s1 = g_esrc[e + 1];
        float4 v0 = *(const float4*)&h[(size_t)s0 * 128 + base];
        float4 v1 = *(const float4*)&h[(size_t)s1 * 128 + base];
        a0 += v0.x + v1.x; a1 += v0.y + v1.y; a2 += v0.z + v1.z; a3 += v0.w + v1.w;
    }
    if (e < end) {
        int s0 = g_esrc[e];
        float4 v0 = *(const float4*)&h[(size_t)s0 * 128 + base];
        a0 += v0.x; a1 += v0.y; a2 += v0.z; a3 += v0.w;
    }
    float nd = g_ndst[gw];
    float4 bb = *(const float4*)&bias[base];
    float4 r;
    r.x = fmaxf(fmaf(a0, nd, bb.x), 0.f);
    r.y = fmaxf(fmaf(a1, nd, bb.y), 0.f);
    r.z = fmaxf(fmaf(a2, nd, bb.z), 0.f);
    r.w = fmaxf(fmaf(a3, nd, bb.w), 0.f);
    *(float4*)&out[(size_t)gw * 128 + base] = r;
}

// warp per node, F=64: lane owns 2 contiguous floats (float2 loads)
__global__ void __launch_bounds__(256) agg64_kernel(
    const float* __restrict__ h, const float* __restrict__ bias,
    float* __restrict__ out)
{
    int gw   = (blockIdx.x * 256 + threadIdx.x) >> 5;
    int lane = threadIdx.x & 31;
    if (gw >= NN) return;
    int base = lane * 2;
    float a0 = 0.f, a1 = 0.f;
    int e = g_off[gw], end = g_off[gw + 1];
    for (; e + 1 < end; e += 2) {
        int s0 = g_esrc[e], s1 = g_esrc[e + 1];
        float2 v0 = *(const float2*)&h[(size_t)s0 * 64 + base];
        float2 v1 = *(const float2*)&h[(size_t)s1 * 64 + base];
        a0 += v0.x + v1.x; a1 += v0.y + v1.y;
    }
    if (e < end) {
        int s0 = g_esrc[e];
        float2 v0 = *(const float2*)&h[(size_t)s0 * 64 + base];
        a0 += v0.x; a1 += v0.y;
    }
    float nd = g_ndst[gw];
    float2 bb = *(const float2*)&bias[base];
    float2 r;
    r.x = fmaxf(fmaf(a0, nd, bb.x), 0.f);
    r.y = fmaxf(fmaf(a1, nd, bb.y), 0.f);
    *(float2*)&out[(size_t)gw * 64 + base] = r;
}

// ---------------- per-graph mean (graph_ids sorted -> binary search) -------
__global__ void pool_kernel(const int* __restrict__ gids,
                            const float* __restrict__ h,
                            float* __restrict__ out)
{
    __shared__ int s_lo, s_hi;
    const int g = blockIdx.x;
    if (threadIdx.x == 0) {
        int lo = 0, hi = NN;
        while (lo < hi) { int m = (lo + hi) >> 1; if (gids[m] < g) lo = m + 1; else hi = m; }
        s_lo = lo;
        lo = 0; hi = NN;
        while (lo < hi) { int m = (lo + hi) >> 1; if (gids[m] < g + 1) lo = m + 1; else hi = m; }
        s_hi = lo;
    }
    __syncthreads();
    const int lo = s_lo, hi = s_hi;
    const int f = threadIdx.x;   // 64 threads, one feature each
    float a0 = 0.f, a1 = 0.f, a2 = 0.f, a3 = 0.f;
    int n = lo;
    for (; n + 3 < hi; n += 4) {
        a0 += h[(size_t)(n    ) * 64 + f];
        a1 += h[(size_t)(n + 1) * 64 + f];
        a2 += h[(size_t)(n + 2) * 64 + f];
        a3 += h[(size_t)(n + 3) * 64 + f];
    }
    for (; n < hi; n++) a0 += h[(size_t)n * 64 + f];
    float s = (a0 + a1) + (a2 + a3);
    float cnt = (float)(hi - lo);
    out[g * 64 + f] = s / fmaxf(cnt, 1.0f);
}

// ---------------- host side ------------------------------------------------
extern "C" void kernel_launch(void* const* d_in, const int* in_sizes, int n_in,
                              void* d_out, int out_size)
{
    const float* feat = (const float*)d_in[0];
    const float* W1   = (const float*)d_in[1];
    const float* b1   = (const float*)d_in[2];
    const float* W2   = (const float*)d_in[3];
    const float* b2   = (const float*)d_in[4];
    const int*   src  = (const int*)  d_in[5];
    const int*   dst  = (const int*)  d_in[6];
    const int*   gids = (const int*)  d_in[7];
    float*       out  = (float*)      d_out;

    float *p_h = nullptr, *p_x1 = nullptr, *p_h2 = nullptr;
    cudaGetSymbolAddress((void**)&p_h,  g_h);
    cudaGetSymbolAddress((void**)&p_x1, g_x1);
    cudaGetSymbolAddress((void**)&p_h2, g_h2);

    const size_t smem1 = (size_t)(128 * 128 + 64  * 132) * sizeof(float); //  99,328 B
    const size_t smem2 = (size_t)(128 * 64  + 128 * 132) * sizeof(float); // 100,352 B
    cudaFuncSetAttribute(gemm_kernel<64, 128>,
                         cudaFuncAttributeMaxDynamicSharedMemorySize, (int)smem1);
    cudaFuncSetAttribute(gemm_kernel<128, 64>,
                         cudaFuncAttributeMaxDynamicSharedMemorySize, (int)smem2);

    // ---- graph structure (degrees, norms, dst-CSR) — recomputed every call
    zero_deg_kernel<<<(NN + 255) / 256, 256>>>();
    degree_kernel  <<<(NE + 255) / 256, 256>>>(src, dst);
    norm_kernel    <<<(NN + 255) / 256, 256>>>();
    scan_kernel    <<<1, 1024>>>();
    bucket_kernel  <<<(NE + 255) / 256, 256>>>(src, dst);

    // ---- layer 1: h = (x * nsrc) @ W1 ; x1 = relu(CSR_sum(h) * ndst + b1)
    gemm_kernel<64, 128><<<(NN + 63) / 64, 256, smem1>>>(feat, W1, p_h, NN);
    agg128_kernel<<<(NN * 32 + 255) / 256, 256>>>(p_h, b1, p_x1);

    // ---- layer 2: h = (x1 * nsrc) @ W2 ; h2 = relu(CSR_sum(h) * ndst + b2)
    gemm_kernel<128, 64><<<(NN + 127) / 128, 256, smem2>>>(p_x1, W2, p_h, NN);
    agg64_kernel<<<(NN * 32 + 255) / 256, 256>>>(p_h, b2, p_h2);

    // ---- per-graph mean pooling
    pool_kernel<<<NG, 64>>>(gids, p_h2, out);
}

// round 15
// speedup vs baseline: 1.3895x; 1.3895x over previous
#include <cuda_runtime.h>
#include <math.h>

// Problem constants (fixed by the dataset)
#define NN 100000
#define NE 1600000
#define NG 128
#define F1 128   // IN_FEATS
#define F2 64    // OUT_FEATS
#define NBLK ((NN + 1023) / 1024)   // 98 scan blocks

// ---------------- scratch (static device allocations are allowed) ----------
__device__ int   g_deg_out[NN];
__device__ int   g_deg_in[NN];
__device__ float g_nsrc[NN];
__device__ float g_ndst[NN];
__device__ int   g_off[NN + 1];
__device__ int   g_cur[NN];
__device__ int   g_esrc[NE];                    // src ids sorted by dst (CSR payload)
__device__ int   g_bsum[128];                   // per-scan-block sums
__device__ int   g_bsum_ex[128];                // exclusive scan of block sums
__device__ float g_h [(size_t)NN * F1];         // GEMM output buffer (reused: 128w then 64w)
__device__ float g_x1[(size_t)NN * F1];         // layer-1 activation
__device__ float g_h2[(size_t)NN * F2];         // layer-2 activation

// ---------------- f32x2 packed-FMA helpers (FFMA2, PTX-only path) ----------
#define PACK2(d, f)        asm("mov.b64 %0, {%1, %1};" : "=l"(d) : "f"(f))
#define UNPACK2(lo, hi, d) asm("mov.b64 {%0, %1}, %2;" : "=f"(lo), "=f"(hi) : "l"(d))
#define FMA_F32X2(d, a, b) asm("fma.rn.f32x2 %0, %1, %2, %0;" : "+l"(d) : "l"(a), "l"(b))

// ---------------- small prep kernels ---------------------------------------
__global__ void zero_deg_kernel() {
    int i = blockIdx.x * blockDim.x + threadIdx.x;
    if (i < NN) { g_deg_out[i] = 0; g_deg_in[i] = 0; }
}

__global__ void degree_kernel(const int* __restrict__ src, const int* __restrict__ dst) {
    int i = blockIdx.x * blockDim.x + threadIdx.x;
    if (i < NE) {
        atomicAdd(&g_deg_out[src[i]], 1);
        atomicAdd(&g_deg_in [dst[i]], 1);
    }
}

// Phase 1: per-block (1024 elems) sums of deg_in
__global__ void __launch_bounds__(1024) scan_partials_kernel() {
    int i = blockIdx.x * 1024 + threadIdx.x;
    int v = (i < NN) ? g_deg_in[i] : 0;
    __shared__ int red[32];
    #pragma unroll
    for (int o = 16; o > 0; o >>= 1) v += __shfl_down_sync(0xffffffffu, v, o);
    if ((threadIdx.x & 31) == 0) red[threadIdx.x >> 5] = v;
    __syncthreads();
    if (threadIdx.x < 32) {
        int s = red[threadIdx.x];
        #pragma unroll
        for (int o = 16; o > 0; o >>= 1) s += __shfl_down_sync(0xffffffffu, s, o);
        if (threadIdx.x == 0) g_bsum[blockIdx.x] = s;
    }
}

// Phase 2: exclusive scan of the 98 block sums (single tiny block)
__global__ void scan_bsums_kernel() {
    __shared__ int sh[128];
    int t = threadIdx.x;
    sh[t] = (t < NBLK) ? g_bsum[t] : 0;
    __syncthreads();
    for (int o = 1; o < 128; o <<= 1) {
        int val = sh[t];
        int add = (t >= o) ? sh[t - o] : 0;
        __syncthreads();
        sh[t] = val + add;
        __syncthreads();
    }
    if (t < NBLK) g_bsum_ex[t] = (t > 0) ? sh[t - 1] : 0;
}

// Phase 3: intra-block scan + block offset -> g_off/g_cur; also compute norms
__global__ void __launch_bounds__(1024) scan_final_kernel() {
    int b = blockIdx.x;
    int i = b * 1024 + threadIdx.x;
    int v = (i < NN) ? g_deg_in[i] : 0;
    int lane = threadIdx.x & 31, w = threadIdx.x >> 5;
    int x = v;
    #pragma unroll
    for (int o = 1; o < 32; o <<= 1) {
        int u = __shfl_up_sync(0xffffffffu, x, o);
        if (lane >= o) x += u;
    }
    __shared__ int wsum[32];
    if (lane == 31) wsum[w] = x;
    __syncthreads();
    if (w == 0) {
        int s = wsum[lane];
        #pragma unroll
        for (int o = 1; o < 32; o <<= 1) {
            int u = __shfl_up_sync(0xffffffffu, s, o);
            if (lane >= o) s += u;
        }
        wsum[lane] = s;
    }
    __syncthreads();
    int incl = x + ((w > 0) ? wsum[w - 1] : 0) + g_bsum_ex[b];
    if (i < NN) {
        int excl = incl - v;
        g_off[i] = excl;
        g_cur[i] = excl;
        g_nsrc[i] = rsqrtf(fmaxf((float)g_deg_out[i], 1.0f));
        g_ndst[i] = rsqrtf(fmaxf((float)v, 1.0f));
    }
    if (i == NN - 1) g_off[NN] = incl;
}

__global__ void bucket_kernel(const int* __restrict__ src, const int* __restrict__ dst) {
    int i = blockIdx.x * blockDim.x + threadIdx.x;
    if (i < NE) {
        int p = atomicAdd(&g_cur[dst[i]], 1);
        g_esrc[p] = src[i];
    }
}

// ---------------- GEMM: C[n, COLS] = (A[n,128] * nsrc[n]) @ W[128, COLS] ----
// 256 threads/block, ROWS rows per block, 4x8 register tile per thread,
// inner product via packed fma.rn.f32x2 (2 FMAs per issue slot).
template <int ROWS, int COLS>
__global__ void __launch_bounds__(256) gemm_kernel(
    const float* __restrict__ A, const float* __restrict__ W,
    float* __restrict__ C, int nrows)
{
    extern __shared__ float smem[];
    float* Ws = smem;                 // [128][COLS]
    float* As = smem + 128 * COLS;    // [ROWS][132]
    const int tid  = threadIdx.x;
    const int row0 = blockIdx.x * ROWS;

    // stage W (contiguous copy, 16B vectors)
    for (int i = tid * 4; i < 128 * COLS; i += 256 * 4)
        *(float4*)&Ws[i] = *(const float4*)&W[i];

    // stage A, scaled by nsrc, zero-padded past nrows
    for (int i = tid; i < ROWS * 32; i += 256) {
        int r  = i >> 5;
        int kq = (i & 31) << 2;
        int gr = row0 + r;
        float4 v = make_float4(0.f, 0.f, 0.f, 0.f);
        float  nv = 0.f;
        if (gr < nrows) { v = *(const float4*)&A[(size_t)gr * 128 + kq]; nv = g_nsrc[gr]; }
        float4 sv = make_float4(v.x * nv, v.y * nv, v.z * nv, v.w * nv);
        *(float4*)&As[r * 132 + kq] = sv;
    }
    __syncthreads();

    constexpr int CG = COLS / 8;
    const int c0 = (tid % CG) * 8;
    const int r0 = (tid / CG) * 4;

    unsigned long long acc2[4][4];
    #pragma unroll
    for (int r = 0; r < 4; r++)
        #pragma unroll
        for (int c = 0; c < 4; c++) acc2[r][c] = 0ull;

    #pragma unroll 8
    for (int k = 0; k < 128; k++) {
        unsigned long long av[4];
        #pragma unroll
        for (int r = 0; r < 4; r++) {
            float a = As[(r0 + r) * 132 + k];
            PACK2(av[r], a);
        }
        const float* wrow = &Ws[k * COLS + c0];
        ulonglong2 w0 = *(const ulonglong2*)wrow;        // cols c0..c0+3
        ulonglong2 w1 = *(const ulonglong2*)(wrow + 4);  // cols c0+4..c0+7
        unsigned long long bv[4] = {w0.x, w0.y, w1.x, w1.y};
        #pragma unroll
        for (int r = 0; r < 4; r++)
            #pragma unroll
            for (int c = 0; c < 4; c++)
                FMA_F32X2(acc2[r][c], av[r], bv[c]);
    }

    #pragma unroll
    for (int r = 0; r < 4; r++) {
        int gr = row0 + r0 + r;
        if (gr < nrows) {
            float o[8];
            #pragma unroll
            for (int c = 0; c < 4; c++)
                UNPACK2(o[2 * c], o[2 * c + 1], acc2[r][c]);
            *(float4*)&C[(size_t)gr * COLS + c0]     = make_float4(o[0], o[1], o[2], o[3]);
            *(float4*)&C[(size_t)gr * COLS + c0 + 4] = make_float4(o[4], o[5], o[6], o[7]);
        }
    }
}

// ---------------- CSR gather aggregation + norm_dst + bias + relu ----------
// warp per node, F=128: lane owns 4 contiguous floats (float4 loads)
__global__ void __launch_bounds__(256) agg128_kernel(
    const float* __restrict__ h, const float* __restrict__ bias,
    float* __restrict__ out)
{
    int gw   = (blockIdx.x * 256 + threadIdx.x) >> 5;
    int lane = threadIdx.x & 31;
    if (gw >= NN) return;
    int base = lane * 4;
    float a0 = 0.f, a1 = 0.f, a2 = 0.f, a3 = 0.f;
    int e = g_off[gw], end = g_off[gw + 1];
    for (; e + 1 < end; e += 2) {
        int s0 = g_esrc[e], s1 = g_esrc[e + 1];
        float4 v0 = *(const float4*)&h[(size_t)s0 * 128 + base];
        float4 v1 = *(const float4*)&h[(size_t)s1 * 128 + base];
        a0 += v0.x + v1.x; a1 += v0.y + v1.y; a2 += v0.z + v1.z; a3 += v0.w + v1.w;
    }
    if (e < end) {
        int s0 = g_esrc[e];
        float4 v0 = *(const float4*)&h[(size_t)s0 * 128 + base];
        a0 += v0.x; a1 += v0.y; a2 += v0.z; a3 += v0.w;
    }
    float nd = g_ndst[gw];
    float4 bb = *(const float4*)&bias[base];
    float4 r;
    r.x = fmaxf(fmaf(a0, nd, bb.x), 0.f);
    r.y = fmaxf(fmaf(a1, nd, bb.y), 0.f);
    r.z = fmaxf(fmaf(a2, nd, bb.z), 0.f);
    r.w = fmaxf(fmaf(a3, nd, bb.w), 0.f);
    *(float4*)&out[(size_t)gw * 128 + base] = r;
}

// warp per node, F=64: lane owns 2 contiguous floats (float2 loads)
__global__ void __launch_bounds__(256) agg64_kernel(
    const float* __restrict__ h, const float* __restrict__ bias,
    float* __restrict__ out)
{
    int gw   = (blockIdx.x * 256 + threadIdx.x) >> 5;
    int lane = threadIdx.x & 31;
    if (gw >= NN) return;
    int base = lane * 2;
    float a0 = 0.f, a1 = 0.f;
    int e = g_off[gw], end = g_off[gw + 1];
    for (; e + 1 < end; e += 2) {
        int s0 = g_esrc[e], s1 = g_esrc[e + 1];
        float2 v0 = *(const float2*)&h[(size_t)s0 * 64 + base];
        float2 v1 = *(const float2*)&h[(size_t)s1 * 64 + base];
        a0 += v0.x + v1.x; a1 += v0.y + v1.y;
    }
    if (e < end) {
        int s0 = g_esrc[e];
        float2 v0 = *(const float2*)&h[(size_t)s0 * 64 + base];
        a0 += v0.x; a1 += v0.y;
    }
    float nd = g_ndst[gw];
    float2 bb = *(const float2*)&bias[base];
    float2 r;
    r.x = fmaxf(fmaf(a0, nd, bb.x), 0.f);
    r.y = fmaxf(fmaf(a1, nd, bb.y), 0.f);
    *(float2*)&out[(size_t)gw * 64 + base] = r;
}

// ---------------- per-graph mean (graph_ids sorted -> binary search) -------
// 512 threads: 8 node-strided groups of 64 feature lanes + smem reduce.
__global__ void __launch_bounds__(512) pool_kernel(
    const int* __restrict__ gids, const float* __restrict__ h,
    float* __restrict__ out)
{
    __shared__ int s_lo, s_hi;
    __shared__ float red[8][64];
    const int g = blockIdx.x;
    if (threadIdx.x == 0) {
        int lo = 0, hi = NN;
        while (lo < hi) { int m = (lo + hi) >> 1; if (gids[m] < g) lo = m + 1; else hi = m; }
        s_lo = lo;
        lo = 0; hi = NN;
        while (lo < hi) { int m = (lo + hi) >> 1; if (gids[m] < g + 1) lo = m + 1; else hi = m; }
        s_hi = lo;
    }
    __syncthreads();
    const int lo = s_lo, hi = s_hi;
    const int grp = threadIdx.x >> 6;   // 0..7
    const int f   = threadIdx.x & 63;
    float a = 0.f, b = 0.f;
    int n = lo + grp;
    for (; n + 8 < hi; n += 16) {
        a += h[(size_t)n * 64 + f];
        b += h[(size_t)(n + 8) * 64 + f];
    }
    if (n < hi) a += h[(size_t)n * 64 + f];
    red[grp][f] = a + b;
    __syncthreads();
    if (grp == 0) {
        float s = 0.f;
        #pragma unroll
        for (int q = 0; q < 8; q++) s += red[q][f];
        out[g * 64 + f] = s / fmaxf((float)(hi - lo), 1.0f);
    }
}

// ---------------- host side ------------------------------------------------
extern "C" void kernel_launch(void* const* d_in, const int* in_sizes, int n_in,
                              void* d_out, int out_size)
{
    const float* feat = (const float*)d_in[0];
    const float* W1   = (const float*)d_in[1];
    const float* b1   = (const float*)d_in[2];
    const float* W2   = (const float*)d_in[3];
    const float* b2   = (const float*)d_in[4];
    const int*   src  = (const int*)  d_in[5];
    const int*   dst  = (const int*)  d_in[6];
    const int*   gids = (const int*)  d_in[7];
    float*       out  = (float*)      d_out;

    float *p_h = nullptr, *p_x1 = nullptr, *p_h2 = nullptr;
    cudaGetSymbolAddress((void**)&p_h,  g_h);
    cudaGetSymbolAddress((void**)&p_x1, g_x1);
    cudaGetSymbolAddress((void**)&p_h2, g_h2);

    const size_t smem1 = (size_t)(128 * 128 + 64  * 132) * sizeof(float); //  99,328 B
    const size_t smem2 = (size_t)(128 * 64  + 128 * 132) * sizeof(float); // 100,352 B
    cudaFuncSetAttribute(gemm_kernel<64, 128>,
                         cudaFuncAttributeMaxDynamicSharedMemorySize, (int)smem1);
    cudaFuncSetAttribute(gemm_kernel<128, 64>,
                         cudaFuncAttributeMaxDynamicSharedMemorySize, (int)smem2);

    // ---- graph structure (degrees, norms, dst-CSR) — recomputed every call
    zero_deg_kernel     <<<(NN + 255) / 256, 256>>>();
    degree_kernel       <<<(NE + 255) / 256, 256>>>(src, dst);
    scan_partials_kernel<<<NBLK, 1024>>>();
    scan_bsums_kernel   <<<1, 128>>>();
    scan_final_kernel   <<<NBLK, 1024>>>();            // also computes norms
    bucket_kernel       <<<(NE + 255) / 256, 256>>>(src, dst);

    // ---- layer 1: h = (x * nsrc) @ W1 ; x1 = relu(CSR_sum(h) * ndst + b1)
    gemm_kernel<64, 128><<<(NN + 63) / 64, 256, smem1>>>(feat, W1, p_h, NN);
    agg128_kernel<<<(NN * 32 + 255) / 256, 256>>>(p_h, b1, p_x1);

    // ---- layer 2: h = (x1 * nsrc) @ W2 ; h2 = relu(CSR_sum(h) * ndst + b2)
    gemm_kernel<128, 64><<<(NN + 127) / 128, 256, smem2>>>(p_x1, W2, p_h, NN);
    agg64_kernel<<<(NN * 32 + 255) / 256, 256>>>(p_h, b2, p_h2);

    // ---- per-graph mean pooling
    pool_kernel<<<NG, 512>>>(gids, p_h2, out);
}

// round 17
// speedup vs baseline: 1.8985x; 1.3663x over previous
#include <cuda_runtime.h>
#include <cuda_bf16.h>
#include <math.h>
#include <stdint.h>

// Problem constants (fixed by the dataset)
#define NN 100000
#define NE 1600000
#define NG 128
#define F1 128   // IN_FEATS
#define F2 64    // OUT_FEATS
#define NBLK ((NN + 1023) / 1024)   // 98 scan blocks

// ---------------- scratch (static device allocations are allowed) ----------
__device__ int   g_deg_out[NN];
__device__ int   g_deg_in[NN];
__device__ float g_nsrc[NN];
__device__ float g_ndst[NN];
__device__ int   g_off[NN + 1];
__device__ int   g_cur[NN];
__device__ int   g_esrc[NE];                    // src ids sorted by dst (CSR payload)
__device__ int   g_bsum[128];                   // per-scan-block sums
__device__ int   g_bsum_ex[128];                // exclusive scan of block sums
__device__ float g_h [(size_t)NN * F1];         // GEMM output buffer (reused: 128w then 64w)
__device__ float g_x1[(size_t)NN * F1];         // layer-1 activation
__device__ float g_h2[(size_t)NN * F2];         // layer-2 activation

// ---------------- warp-MMA helpers (baseline sm_80+ PTX, no 'a' features) --
__device__ __forceinline__ uint32_t smem_u32(const void* p) {
    uint32_t a;
    asm("{ .reg .u64 t; cvta.to.shared.u64 t, %1; cvt.u32.u64 %0, t; }" : "=r"(a) : "l"(p));
    return a;
}
#define LDSM4(r, addr) \
    asm volatile("ldmatrix.sync.aligned.m8n8.x4.shared.b16 {%0,%1,%2,%3}, [%4];" \
        : "=r"((r)[0]), "=r"((r)[1]), "=r"((r)[2]), "=r"((r)[3]) : "r"(addr))
#define MMA16816(d, a, b0, b1) \
    asm volatile("mma.sync.aligned.m16n8k16.row.col.f32.bf16.bf16.f32 " \
        "{%0,%1,%2,%3}, {%4,%5,%6,%7}, {%8,%9}, {%0,%1,%2,%3};" \
        : "+f"((d)[0]), "+f"((d)[1]), "+f"((d)[2]), "+f"((d)[3]) \
        : "r"((a)[0]), "r"((a)[1]), "r"((a)[2]), "r"((a)[3]), "r"(b0), "r"(b1))

// ---------------- small prep kernels ---------------------------------------
__global__ void degree_kernel(const int* __restrict__ src, const int* __restrict__ dst) {
    int i = blockIdx.x * blockDim.x + threadIdx.x;
    if (i < NE) {
        atomicAdd(&g_deg_out[src[i]], 1);
        atomicAdd(&g_deg_in [dst[i]], 1);
    }
}

__global__ void __launch_bounds__(1024) scan_partials_kernel() {
    int i = blockIdx.x * 1024 + threadIdx.x;
    int v = (i < NN) ? g_deg_in[i] : 0;
    __shared__ int red[32];
    #pragma unroll
    for (int o = 16; o > 0; o >>= 1) v += __shfl_down_sync(0xffffffffu, v, o);
    if ((threadIdx.x & 31) == 0) red[threadIdx.x >> 5] = v;
    __syncthreads();
    if (threadIdx.x < 32) {
        int s = red[threadIdx.x];
        #pragma unroll
        for (int o = 16; o > 0; o >>= 1) s += __shfl_down_sync(0xffffffffu, s, o);
        if (threadIdx.x == 0) g_bsum[blockIdx.x] = s;
    }
}

__global__ void scan_bsums_kernel() {
    __shared__ int sh[128];
    int t = threadIdx.x;
    sh[t] = (t < NBLK) ? g_bsum[t] : 0;
    __syncthreads();
    for (int o = 1; o < 128; o <<= 1) {
        int val = sh[t];
        int add = (t >= o) ? sh[t - o] : 0;
        __syncthreads();
        sh[t] = val + add;
        __syncthreads();
    }
    if (t < NBLK) g_bsum_ex[t] = (t > 0) ? sh[t - 1] : 0;
}

__global__ void __launch_bounds__(1024) scan_final_kernel() {
    int b = blockIdx.x;
    int i = b * 1024 + threadIdx.x;
    int v = (i < NN) ? g_deg_in[i] : 0;
    int lane = threadIdx.x & 31, w = threadIdx.x >> 5;
    int x = v;
    #pragma unroll
    for (int o = 1; o < 32; o <<= 1) {
        int u = __shfl_up_sync(0xffffffffu, x, o);
        if (lane >= o) x += u;
    }
    __shared__ int wsum[32];
    if (lane == 31) wsum[w] = x;
    __syncthreads();
    if (w == 0) {
        int s = wsum[lane];
        #pragma unroll
        for (int o = 1; o < 32; o <<= 1) {
            int u = __shfl_up_sync(0xffffffffu, s, o);
            if (lane >= o) s += u;
        }
        wsum[lane] = s;
    }
    __syncthreads();
    int incl = x + ((w > 0) ? wsum[w - 1] : 0) + g_bsum_ex[b];
    if (i < NN) {
        int excl = incl - v;
        g_off[i] = excl;
        g_cur[i] = excl;
        g_nsrc[i] = rsqrtf(fmaxf((float)g_deg_out[i], 1.0f));
        g_ndst[i] = rsqrtf(fmaxf((float)v, 1.0f));
    }
    if (i == NN - 1) g_off[NN] = incl;
}

__global__ void bucket_kernel(const int* __restrict__ src, const int* __restrict__ dst) {
    int i = blockIdx.x * blockDim.x + threadIdx.x;
    if (i < NE) {
        int p = atomicAdd(&g_cur[dst[i]], 1);
        g_esrc[p] = src[i];
    }
}

// ============ HMMA GEMM: C[n,NCOLS] = (A[n,128]*nsrc[n]) @ W[128,NCOLS] =====
// 3-term bf16 split (Ah·Bh + Ah·Bl + Al·Bh) into one fp32 accumulator.
// smem tiles use a 272-byte row stride (136 bf16): consecutive rows shift
// 16B in bank space -> conflict-free ldmatrix for 8-row groups.
template <int NCOLS>
__global__ void __launch_bounds__(256) mma_gemm_kernel(
    const float* __restrict__ A, const float* __restrict__ W,
    float* __restrict__ C, int nrows)
{
    constexpr int RS    = 272;            // smem row stride in bytes
    constexpr int ATILE = 128 * RS;       // 34816 B per A split
    constexpr int WTILE = NCOLS * RS;     // per W^T split
    extern __shared__ char sm[];
    char* AHp = sm;
    char* ALp = sm + ATILE;
    char* WHp = sm + 2 * ATILE;
    char* WLp = sm + 2 * ATILE + WTILE;

    const int tid  = threadIdx.x;
    const int wid  = tid >> 5;
    const int lane = tid & 31;
    const int row0 = blockIdx.x * 128;

    // ---- stage A tile: scale by nsrc, split into hi/lo bf16
    for (int idx = tid; idx < 128 * 32; idx += 256) {
        int row = idx >> 5, kq = (idx & 31) << 2;
        int gr  = row0 + row;
        float4 v = make_float4(0.f, 0.f, 0.f, 0.f);
        float  nv = 0.f;
        if (gr < nrows) { v = ((const float4*)A)[(size_t)gr * 32 + (idx & 31)]; nv = g_nsrc[gr]; }
        float e[4] = {v.x * nv, v.y * nv, v.z * nv, v.w * nv};
        unsigned short hh[4], ll[4];
        #pragma unroll
        for (int j = 0; j < 4; j++) {
            __nv_bfloat16 bh = __float2bfloat16_rn(e[j]);
            float res = e[j] - __bfloat162float(bh);
            __nv_bfloat16 bl = __float2bfloat16_rn(res);
            hh[j] = __bfloat16_as_ushort(bh);
            ll[j] = __bfloat16_as_ushort(bl);
        }
        uint32_t off = (uint32_t)row * RS + (uint32_t)kq * 2;   // 8B aligned
        *(uint2*)(AHp + off) = make_uint2((uint32_t)hh[0] | ((uint32_t)hh[1] << 16),
                                          (uint32_t)hh[2] | ((uint32_t)hh[3] << 16));
        *(uint2*)(ALp + off) = make_uint2((uint32_t)ll[0] | ((uint32_t)ll[1] << 16),
                                          (uint32_t)ll[2] | ((uint32_t)ll[3] << 16));
    }

    // ---- stage W^T tile [NCOLS n][128 k], split hi/lo (coalesced gmem read)
    for (int idx = tid; idx < 128 * NCOLS; idx += 256) {
        int k = idx / NCOLS, n = idx % NCOLS;
        float e = W[idx];
        __nv_bfloat16 bh = __float2bfloat16_rn(e);
        float res = e - __bfloat162float(bh);
        __nv_bfloat16 bl = __float2bfloat16_rn(res);
        uint32_t off = (uint32_t)n * RS + (uint32_t)k * 2;
        *(__nv_bfloat16*)(WHp + off) = bh;
        *(__nv_bfloat16*)(WLp + off) = bl;
    }
    __syncthreads();

    // ---- warp-level MMA mainloop: warp owns rows m0..m0+15, all NCOLS
    const int m0 = wid * 16;
    float acc[NCOLS / 8][4];
    #pragma unroll
    for (int t = 0; t < NCOLS / 8; t++)
        #pragma unroll
        for (int j = 0; j < 4; j++) acc[t][j] = 0.f;

    // per-lane ldmatrix address components
    const int grp = lane >> 3, li = lane & 7;
    // A x4 order: (m0-7,k0-7)(m8-15,k0-7)(m0-7,k8-15)(m8-15,k8-15)
    const uint32_t aoff = (uint32_t)(m0 + li + ((grp & 1) << 3)) * RS + ((grp >> 1) << 4);
    // B x4 order: (n0-7,k0-7)(n0-7,k8-15)(n8-15,k0-7)(n8-15,k8-15)
    const uint32_t boff = (uint32_t)(li + ((grp >> 1) << 3)) * RS + ((grp & 1) << 4);

    const uint32_t ah_b = smem_u32(AHp), al_b = smem_u32(ALp);
    const uint32_t wh_b = smem_u32(WHp), wl_b = smem_u32(WLp);

    #pragma unroll
    for (int ks = 0; ks < 8; ks++) {
        const uint32_t kb = (uint32_t)ks * 32;   // 16 bf16 = 32 bytes
        uint32_t ah[4], al[4];
        LDSM4(ah, ah_b + aoff + kb);
        LDSM4(al, al_b + aoff + kb);
        #pragma unroll
        for (int np = 0; np < NCOLS / 16; np++) {
            const uint32_t nb = (uint32_t)np * 16 * RS;
            uint32_t bh[4], bl[4];
            LDSM4(bh, wh_b + nb + boff + kb);
            LDSM4(bl, wl_b + nb + boff + kb);
            MMA16816(acc[2 * np],     ah, bh[0], bh[1]);
            MMA16816(acc[2 * np],     ah, bl[0], bl[1]);
            MMA16816(acc[2 * np],     al, bh[0], bh[1]);
            MMA16816(acc[2 * np + 1], ah, bh[2], bh[3]);
            MMA16816(acc[2 * np + 1], ah, bl[2], bl[3]);
            MMA16816(acc[2 * np + 1], al, bh[2], bh[3]);
        }
    }

    // ---- epilogue: c-frag m16n8 layout -> fp32 stores
    const int r_hi  = row0 + m0 + (lane >> 2);
    const int cbase = (lane & 3) * 2;
    #pragma unroll
    for (int nt = 0; nt < NCOLS / 8; nt++) {
        int col = nt * 8 + cbase;
        if (r_hi < nrows)
            *(float2*)&C[(size_t)r_hi * NCOLS + col] = make_float2(acc[nt][0], acc[nt][1]);
        if (r_hi + 8 < nrows)
            *(float2*)&C[(size_t)(r_hi + 8) * NCOLS + col] = make_float2(acc[nt][2], acc[nt][3]);
    }
}

// ---------------- CSR gather aggregation + norm_dst + bias + relu ----------
__global__ void __launch_bounds__(256) agg128_kernel(
    const float* __restrict__ h, const float* __restrict__ bias,
    float* __restrict__ out)
{
    int gw   = (blockIdx.x * 256 + threadIdx.x) >> 5;
    int lane = threadIdx.x & 31;
    if (gw >= NN) return;
    int base = lane * 4;
    float a0 = 0.f, a1 = 0.f, a2 = 0.f, a3 = 0.f;
    int e = g_off[gw], end = g_off[gw + 1];
    for (; e + 3 < end; e += 4) {
        int s0 = g_esrc[e], s1 = g_esrc[e + 1], s2 = g_esrc[e + 2], s3 = g_esrc[e + 3];
        float4 v0 = *(const float4*)&h[(size_t)s0 * 128 + base];
        float4 v1 = *(const float4*)&h[(size_t)s1 * 128 + base];
        float4 v2 = *(const float4*)&h[(size_t)s2 * 128 + base];
        float4 v3 = *(const float4*)&h[(size_t)s3 * 128 + base];
        a0 += (v0.x + v1.x) + (v2.x + v3.x);
        a1 += (v0.y + v1.y) + (v2.y + v3.y);
        a2 += (v0.z + v1.z) + (v2.z + v3.z);
        a3 += (v0.w + v1.w) + (v2.w + v3.w);
    }
    for (; e < end; e++) {
        int s0 = g_esrc[e];
        float4 v0 = *(const float4*)&h[(size_t)s0 * 128 + base];
        a0 += v0.x; a1 += v0.y; a2 += v0.z; a3 += v0.w;
    }
    float nd = g_ndst[gw];
    float4 bb = *(const float4*)&bias[base];
    float4 r;
    r.x = fmaxf(fmaf(a0, nd, bb.x), 0.f);
    r.y = fmaxf(fmaf(a1, nd, bb.y), 0.f);
    r.z = fmaxf(fmaf(a2, nd, bb.z), 0.f);
    r.w = fmaxf(fmaf(a3, nd, bb.w), 0.f);
    *(float4*)&out[(size_t)gw * 128 + base] = r;
}

__global__ void __launch_bounds__(256) agg64_kernel(
    const float* __restrict__ h, const float* __restrict__ bias,
    float* __restrict__ out)
{
    int gw   = (blockIdx.x * 256 + threadIdx.x) >> 5;
    int lane = threadIdx.x & 31;
    if (gw >= NN) return;
    int base = lane * 2;
    float a0 = 0.f, a1 = 0.f;
    int e = g_off[gw], end = g_off[gw + 1];
    for (; e + 3 < end; e += 4) {
        int s0 = g_esrc[e], s1 = g_esrc[e + 1], s2 = g_esrc[e + 2], s3 = g_esrc[e + 3];
        float2 v0 = *(const float2*)&h[(size_t)s0 * 64 + base];
        float2 v1 = *(const float2*)&h[(size_t)s1 * 64 + base];
        float2 v2 = *(const float2*)&h[(size_t)s2 * 64 + base];
        float2 v3 = *(const float2*)&h[(size_t)s3 * 64 + base];
        a0 += (v0.x + v1.x) + (v2.x + v3.x);
        a1 += (v0.y + v1.y) + (v2.y + v3.y);
    }
    for (; e < end; e++) {
        int s0 = g_esrc[e];
        float2 v0 = *(const float2*)&h[(size_t)s0 * 64 + base];
        a0 += v0.x; a1 += v0.y;
    }
    float nd = g_ndst[gw];
    float2 bb = *(const float2*)&bias[base];
    float2 r;
    r.x = fmaxf(fmaf(a0, nd, bb.x), 0.f);
    r.y = fmaxf(fmaf(a1, nd, bb.y), 0.f);
    *(float2*)&out[(size_t)gw * 64 + base] = r;
}

// ---------------- per-graph mean (graph_ids sorted -> binary search) -------
__global__ void __launch_bounds__(512) pool_kernel(
    const int* __restrict__ gids, const float* __restrict__ h,
    float* __restrict__ out)
{
    __shared__ int s_lo, s_hi;
    __shared__ float red[8][64];
    const int g = blockIdx.x;
    if (threadIdx.x == 0) {
        int lo = 0, hi = NN;
        while (lo < hi) { int m = (lo + hi) >> 1; if (gids[m] < g) lo = m + 1; else hi = m; }
        s_lo = lo;
        lo = 0; hi = NN;
        while (lo < hi) { int m = (lo + hi) >> 1; if (gids[m] < g + 1) lo = m + 1; else hi = m; }
        s_hi = lo;
    }
    __syncthreads();
    const int lo = s_lo, hi = s_hi;
    const int grp = threadIdx.x >> 6;
    const int f   = threadIdx.x & 63;
    float a = 0.f, b = 0.f;
    int n = lo + grp;
    for (; n + 8 < hi; n += 16) {
        a += h[(size_t)n * 64 + f];
        b += h[(size_t)(n + 8) * 64 + f];
    }
    if (n < hi) a += h[(size_t)n * 64 + f];
    red[grp][f] = a + b;
    __syncthreads();
    if (grp == 0) {
        float s = 0.f;
        #pragma unroll
        for (int q = 0; q < 8; q++) s += red[q][f];
        out[g * 64 + f] = s / fmaxf((float)(hi - lo), 1.0f);
    }
}

// ---------------- host side ------------------------------------------------
extern "C" void kernel_launch(void* const* d_in, const int* in_sizes, int n_in,
                              void* d_out, int out_size)
{
    const float* feat = (const float*)d_in[0];
    const float* W1   = (const float*)d_in[1];
    const float* b1   = (const float*)d_in[2];
    const float* W2   = (const float*)d_in[3];
    const float* b2   = (const float*)d_in[4];
    const int*   src  = (const int*)  d_in[5];
    const int*   dst  = (const int*)  d_in[6];
    const int*   gids = (const int*)  d_in[7];
    float*       out  = (float*)      d_out;

    float *p_h = nullptr, *p_x1 = nullptr, *p_h2 = nullptr;
    int   *p_do = nullptr, *p_di = nullptr;
    cudaGetSymbolAddress((void**)&p_h,  g_h);
    cudaGetSymbolAddress((void**)&p_x1, g_x1);
    cudaGetSymbolAddress((void**)&p_h2, g_h2);
    cudaGetSymbolAddress((void**)&p_do, g_deg_out);
    cudaGetSymbolAddress((void**)&p_di, g_deg_in);

    const int smem1 = 2 * (128 * 272) + 2 * (128 * 272);  // 139,264 B
    const int smem2 = 2 * (128 * 272) + 2 * (64  * 272);  // 104,448 B
    cudaFuncSetAttribute(mma_gemm_kernel<128>,
                         cudaFuncAttributeMaxDynamicSharedMemorySize, smem1);
    cudaFuncSetAttribute(mma_gemm_kernel<64>,
                         cudaFuncAttributeMaxDynamicSharedMemorySize, smem2);

    // ---- graph structure (degrees, norms, dst-CSR) — recomputed every call
    cudaMemsetAsync(p_do, 0, NN * sizeof(int), 0);
    cudaMemsetAsync(p_di, 0, NN * sizeof(int), 0);
    degree_kernel       <<<(NE + 255) / 256, 256>>>(src, dst);
    scan_partials_kernel<<<NBLK, 1024>>>();
    scan_bsums_kernel   <<<1, 128>>>();
    scan_final_kernel   <<<NBLK, 1024>>>();            // also computes norms
    bucket_kernel       <<<(NE + 255) / 256, 256>>>(src, dst);

    const int ntiles = (NN + 127) / 128;               // 782

    // ---- layer 1: h = (x * nsrc) @ W1 ; x1 = relu(CSR_sum(h) * ndst + b1)
    mma_gemm_kernel<128><<<ntiles, 256, smem1>>>(feat, W1, p_h, NN);
    agg128_kernel<<<(NN * 32 + 255) / 256, 256>>>(p_h, b1, p_x1);

    // ---- layer 2: h = (x1 * nsrc) @ W2 ; h2 = relu(CSR_sum(h) * ndst + b2)
    mma_gemm_kernel<64><<<ntiles, 256, smem2>>>(p_x1, W2, p_h, NN);
    agg64_kernel<<<(NN * 32 + 255) / 256, 256>>>(p_h, b2, p_h2);

    // ---- per-graph mean pooling
    pool_kernel<<<NG, 512>>>(gids, p_h2, out);
}